// round 13
// baseline (speedup 1.0000x reference)
#include <cuda_runtime.h>
#include <cuda_bf16.h>
#include <cstdint>
#include <cstddef>

#define TSTEPS 512
#define NBATCH 64
#define HID    1024
#define NGATE  4096
#define TBROWS (TSTEPS * NBATCH)          // 32768
#define GH     (NGATE * HID)              // 4194304 = 2^22
#define XLEN   ((size_t)TBROWS * HID)     // 33554432

typedef __nv_bfloat16 bf16;

// lstm_layer dynamic smem (bytes):
//   A chunks: [0, 98304)  = group(4) x stage(3) x part(hi/lo) x 4096 (64x64B, SWZ)
//   B hi    : [98304 , 163840)  32 tiles x 2048 (32x64B rows, SWZ), resident
//   B lo    : [163840, 229376)
//   sGp (4x64x33 fp32 = 33792B) aliases the A region after the k-loop
#define A_G_STRIDE  24576u
#define A_ST_STRIDE 8192u
#define A_PART      4096u
#define SM_B_HI     98304u
#define SM_B_LO     163840u
#define SM_LSTM_TOTAL 229376
#define SWZ(x) ((x) ^ (((x) >> 3) & 0x30))

// gemm_xw static smem: 2 stages x 24576B
//   stage s: Ahi +0 (8192) | Alo +8192 | Bhi +16384 (4096) | Blo +20480
#define G_ST 24576u

// ---------------- static device scratch (no runtime allocation) -------------
__device__ float    g_xw[(size_t)TBROWS * NGATE];     // 536 MB, per-layer reuse
__device__ bf16     g_ahi[XLEN];                      // x splits -> h1 -> h2
__device__ bf16     g_alo[XLEN];
__device__ bf16     g_whi[4ull * GH];                 // wih0, whh0, wih1, whh1
__device__ bf16     g_wlo[4ull * GH];
__device__ float    g_bias[2 * NGATE];
__device__ unsigned g_barcnt;                         // monotonic grid barrier

// ---------------- helpers ---------------------------------------------------
static __device__ __forceinline__ uint32_t sptr(const void* p) {
    return (uint32_t)__cvta_generic_to_shared(p);
}
static __device__ __forceinline__ void ldsm4(uint32_t* r, uint32_t a) {
    asm volatile("ldmatrix.sync.aligned.m8n8.x4.shared.b16 {%0,%1,%2,%3}, [%4];\n"
                 : "=r"(r[0]), "=r"(r[1]), "=r"(r[2]), "=r"(r[3]) : "r"(a));
}
static __device__ __forceinline__ void mma_nt(float* d, const uint32_t* a,
                                              uint32_t b0, uint32_t b1) {
    asm volatile(
        "mma.sync.aligned.m16n8k16.row.col.f32.bf16.bf16.f32 "
        "{%0,%1,%2,%3},{%4,%5,%6,%7},{%8,%9},{%0,%1,%2,%3};\n"
        : "+f"(d[0]), "+f"(d[1]), "+f"(d[2]), "+f"(d[3])
        : "r"(a[0]), "r"(a[1]), "r"(a[2]), "r"(a[3]), "r"(b0), "r"(b1));
}
static __device__ __forceinline__ void cpa16(uint32_t dst, const void* src) {
    asm volatile("cp.async.cg.shared.global [%0], [%1], 16;\n" :: "r"(dst), "l"(src));
}
#define CP_COMMIT() asm volatile("cp.async.commit_group;\n")
#define CP_WAIT1()  asm volatile("cp.async.wait_group 1;\n")
#define CP_WAIT0()  asm volatile("cp.async.wait_group 0;\n")

// fast activations via MUFU ex2 path (~2 ulp): error ~1e-6, far under budget
static __device__ __forceinline__ float sigf(float x) {
    return __fdividef(1.f, 1.f + __expf(-x));
}
static __device__ __forceinline__ float tanhf_fast(float x) {
    float e = __expf(-2.f * fabsf(x));
    float t = __fdividef(1.f - e, 1.f + e);
    return copysignf(t, x);
}

// Grid barrier over NCTA CTAs: monotonic ticket counter (graph-replay safe).
template <unsigned NCTA>
static __device__ __forceinline__ void grid_barrier() {
    __syncthreads();
    if (threadIdx.x == 0) {
        __threadfence();
        unsigned tk = atomicAdd(&g_barcnt, 1u);
        unsigned target = (tk / NCTA) * NCTA + NCTA;
        while ((int)(*(volatile unsigned*)&g_barcnt - target) < 0) {}
        __threadfence();
    }
    __syncthreads();
}

// ---------------- prep: fp32 -> bf16 hi/lo splits (x + 4 weights), biases ----
__global__ void prep_split(const float* __restrict__ x,
                           const float* __restrict__ w0, const float* __restrict__ w1,
                           const float* __restrict__ w2, const float* __restrict__ w3,
                           bf16* __restrict__ ahi, bf16* __restrict__ alo,
                           bf16* __restrict__ whi, bf16* __restrict__ wlo) {
    const size_t total = XLEN + 4ull * GH;
    for (size_t i = (size_t)blockIdx.x * blockDim.x + threadIdx.x; i < total;
         i += (size_t)gridDim.x * blockDim.x) {
        float v; bf16 *dh, *dl;
        if (i < XLEN) {
            v = x[i]; dh = ahi + i; dl = alo + i;
        } else {
            size_t j = i - XLEN;
            int w = (int)(j >> 22);
            size_t k = j & (GH - 1);
            const float* src = (w == 0) ? w0 : (w == 1) ? w1 : (w == 2) ? w2 : w3;
            v = src[k]; dh = whi + j; dl = wlo + j;
        }
        bf16 h = __float2bfloat16(v);
        *dh = h;
        *dl = __float2bfloat16(v - __bfloat162float(h));
    }
}
__global__ void prep_bias(const float* __restrict__ a0, const float* __restrict__ b0,
                          const float* __restrict__ a1, const float* __restrict__ b1,
                          float* __restrict__ o) {
    int i = blockIdx.x * blockDim.x + threadIdx.x;
    if (i < NGATE) o[i] = a0[i] + b0[i];
    else if (i < 2 * NGATE) o[i] = a1[i - NGATE] + b1[i - NGATE];
}

// ---------------- big GEMM: out[M,4096] = A[M,1024] @ W[4096,1024]^T + bias --
// CTA tile 128x64, BK=32, 256 thr (8 warps = 4 m-quarters x 2 n-halves,
// warp tile 32x32), 2 CTAs/SM, 2-stage cp.async, ONE sync/iter, SWZ 64B rows.
// grid=(n64, m256), n fast so W (16.8MB hi+lo) stays L2-resident.
__global__ __launch_bounds__(256, 2) void gemm_xw(
    const bf16* __restrict__ Ahi, const bf16* __restrict__ Alo,
    const bf16* __restrict__ Whi, const bf16* __restrict__ Wlo,
    const float* __restrict__ bias, float* __restrict__ out) {
    __shared__ __align__(16) unsigned char sraw[49152];   // 2 x 24576
    const uint32_t sb = sptr(sraw);

    const int tid = threadIdx.x, warp = tid >> 5, lane = tid & 31;
    const size_t n0 = (size_t)blockIdx.x * 64, m0 = (size_t)blockIdx.y * 128;
    const int mq = warp & 3, nh = warp >> 2;

    // A loader: thread t -> row t>>1 (0..127), granule cols (t&1)*2, +1
    const int arow = tid >> 1, acb = (tid & 1) * 2;
    const bf16* pAhi = Ahi + (m0 + arow) * HID + acb * 8;
    const bf16* pAlo = Alo + (m0 + arow) * HID + acb * 8;
    const uint32_t adst0 = SWZ((uint32_t)(arow * 64 + acb * 16));
    const uint32_t adst1 = SWZ((uint32_t)(arow * 64 + (acb + 1) * 16));
    // B loader: thread t -> row t>>2 (0..63), granule col t&3
    const int brow = tid >> 2, bcb = tid & 3;
    const bf16* pBhi = Whi + (n0 + brow) * HID + bcb * 8;
    const bf16* pBlo = Wlo + (n0 + brow) * HID + bcb * 8;
    const uint32_t bdst = SWZ((uint32_t)(brow * 64 + bcb * 16));

    // ldsm bases (logical; SWZ at use)
    const uint32_t a_row0 = (uint32_t)((mq * 32 + (lane & 15)) * 64);
    const uint32_t a_row1 = a_row0 + 16 * 64;
    const uint32_t b_row0 = (uint32_t)((nh * 32 + (lane & 15)) * 64);
    const uint32_t b_row1 = b_row0 + 16 * 64;
    const uint32_t ac16 = (uint32_t)((lane >> 4) * 16);

    float acc[2][4][4];
#pragma unroll
    for (int a = 0; a < 2; ++a)
#pragma unroll
        for (int b = 0; b < 4; ++b)
#pragma unroll
            for (int q = 0; q < 4; ++q) acc[a][b][q] = 0.f;

#define GEMM_ISSUE(it, s) do {                                       \
        const uint32_t o = sb + (uint32_t)(s) * G_ST;                \
        cpa16(o + adst0,          pAhi + (it) * 32);                 \
        cpa16(o + adst1,          pAhi + (it) * 32 + 8);             \
        cpa16(o + 8192 + adst0,   pAlo + (it) * 32);                 \
        cpa16(o + 8192 + adst1,   pAlo + (it) * 32 + 8);             \
        cpa16(o + 16384 + bdst,   pBhi + (it) * 32);                 \
        cpa16(o + 20480 + bdst,   pBlo + (it) * 32);                 \
        CP_COMMIT(); } while (0)

    GEMM_ISSUE(0, 0);
    for (int it = 0; it < 32; ++it) {
        CP_WAIT0();
        __syncthreads();
        if (it < 31) GEMM_ISSUE(it + 1, (it + 1) & 1);
        const uint32_t ab = sb + (uint32_t)(it & 1) * G_ST;
#pragma unroll
        for (int kk = 0; kk < 2; ++kk) {
            const uint32_t ca = ac16 + (uint32_t)kk * 32;
            uint32_t ah0[4], ah1[4], al0[4], al1[4];
            ldsm4(ah0, ab + SWZ(a_row0 + ca));
            ldsm4(ah1, ab + SWZ(a_row1 + ca));
            ldsm4(al0, ab + 8192 + SWZ(a_row0 + ca));
            ldsm4(al1, ab + 8192 + SWZ(a_row1 + ca));
            uint32_t bhA[4], bhB[4], blA[4], blB[4];
            ldsm4(bhA, ab + 16384 + SWZ(b_row0 + ca));
            ldsm4(bhB, ab + 16384 + SWZ(b_row1 + ca));
            ldsm4(blA, ab + 20480 + SWZ(b_row0 + ca));
            ldsm4(blB, ab + 20480 + SWZ(b_row1 + ca));
            mma_nt(acc[0][0], ah0, bhA[0], bhA[2]);
            mma_nt(acc[0][0], ah0, blA[0], blA[2]);
            mma_nt(acc[0][0], al0, bhA[0], bhA[2]);
            mma_nt(acc[0][1], ah0, bhA[1], bhA[3]);
            mma_nt(acc[0][1], ah0, blA[1], blA[3]);
            mma_nt(acc[0][1], al0, bhA[1], bhA[3]);
            mma_nt(acc[0][2], ah0, bhB[0], bhB[2]);
            mma_nt(acc[0][2], ah0, blB[0], blB[2]);
            mma_nt(acc[0][2], al0, bhB[0], bhB[2]);
            mma_nt(acc[0][3], ah0, bhB[1], bhB[3]);
            mma_nt(acc[0][3], ah0, blB[1], blB[3]);
            mma_nt(acc[0][3], al0, bhB[1], bhB[3]);
            mma_nt(acc[1][0], ah1, bhA[0], bhA[2]);
            mma_nt(acc[1][0], ah1, blA[0], blA[2]);
            mma_nt(acc[1][0], al1, bhA[0], bhA[2]);
            mma_nt(acc[1][1], ah1, bhA[1], bhA[3]);
            mma_nt(acc[1][1], ah1, blA[1], blA[3]);
            mma_nt(acc[1][1], al1, bhA[1], bhA[3]);
            mma_nt(acc[1][2], ah1, bhB[0], bhB[2]);
            mma_nt(acc[1][2], ah1, blB[0], blB[2]);
            mma_nt(acc[1][2], al1, bhB[0], bhB[2]);
            mma_nt(acc[1][3], ah1, bhB[1], bhB[3]);
            mma_nt(acc[1][3], ah1, blB[1], blB[3]);
            mma_nt(acc[1][3], al1, bhB[1], bhB[3]);
        }
    }
#undef GEMM_ISSUE
    __syncthreads();

#pragma unroll
    for (int mb = 0; mb < 2; ++mb) {
        const size_t r = m0 + mq * 32 + mb * 16 + (lane >> 2);
#pragma unroll
        for (int nb = 0; nb < 4; ++nb) {
            const size_t col = n0 + nh * 32 + nb * 8 + (lane & 3) * 2;
            const float b0 = bias[col], b1 = bias[col + 1];
            float2* o0 = (float2*)(out + r * NGATE + col);
            float2* o1 = (float2*)(out + (r + 8) * NGATE + col);
            *o0 = make_float2(acc[mb][nb][0] + b0, acc[mb][nb][1] + b1);
            *o1 = make_float2(acc[mb][nb][2] + b0, acc[mb][nb][3] + b1);
        }
    }
}

// ---------------- persistent recurrent layer ---------------------------------
// 128 CTAs. CTA: 64 batch x 8 h-cols x 4 gates (N=32), K=1024.
// 8 warps = 4 k-groups (8 k-tiles each) x 2 m-halves; warp MMA tile 32m x 32n.
// B (W_hh hi/lo) resident in SMEM (SWZ 64B rows); A streamed per group,
// 3-stage cp.async, ONE syncthreads per round. xw[t+1] prefetched pre-barrier.
__global__ __launch_bounds__(256) void lstm_layer(
    const bf16* __restrict__ Whi, const bf16* __restrict__ Wlo,   // whh splits
    const float* __restrict__ xw,                                 // [512][64][4096]
    bf16* __restrict__ hHi, bf16* __restrict__ hLo,               // slot t out / t-1 in
    float* __restrict__ outF) {                                   // null for layer 0
    extern __shared__ __align__(16) unsigned char sraw[];
    float* sGp = (float*)sraw;                 // [4][64][33] fp32, aliases A region
    const uint32_t sb = sptr(sraw);

    const int tid = threadIdx.x, warp = tid >> 5, lane = tid & 31;
    const int hs = blockIdx.x * 8;
    const int kg = warp >> 1;                  // k-group 0..3 (k-tiles 8kg..8kg+7)
    const int mhalf = warp & 1;                // rows mhalf*32 .. +31

    // ---- one-time resident B load (threads 0-127 hi, 128-255 lo) ----
    {
        const int jj = (tid & 127) >> 2, cb = tid & 3;
        const int wrow = (jj >> 3) * HID + hs + (jj & 7);     // gate*1024 + h-col
        const bf16* pB = ((tid < 128) ? Whi : Wlo) + (size_t)wrow * HID + cb * 8;
        const uint32_t dstB = sb + ((tid < 128) ? SM_B_HI : SM_B_LO)
                            + SWZ((uint32_t)(jj * 64 + cb * 16));
#pragma unroll 4
        for (int it = 0; it < 32; ++it)
            cpa16(dstB + (uint32_t)it * 2048, pB + it * 32);
        CP_COMMIT();
        CP_WAIT0();
        __syncthreads();
    }

    // ---- A loader mapping: each thread owns one 16B granule per (group, part)
    const int arow = tid >> 2, acb = tid & 3;                 // 64 rows x 4 colblocks
    const size_t asrc = (size_t)arow * HID + acb * 8;
    const uint32_t adst = SWZ((uint32_t)(arow * 64 + acb * 16));

    // ---- ldsm bases (logical offsets; SWZ applied at use) ----
    const uint32_t aGbase = sb + (uint32_t)kg * A_G_STRIDE;
    const uint32_t a_row0 = (uint32_t)((mhalf * 32 + (lane & 15)) * 64);
    const uint32_t a_row1 = a_row0 + 16 * 64;
    const uint32_t ac16   = (uint32_t)((lane >> 4) * 16);     // + kk*32
    const uint32_t b_row0 = (uint32_t)((lane & 15) * 64);
    const uint32_t b_row1 = b_row0 + 16 * 64;

    // epilogue element mapping (2 per thread)
    const int em0 = tid >> 3,         ej0 = tid & 7;
    const int em1 = (tid + 256) >> 3, ej1 = (tid + 256) & 7;

    float creg[2] = {0.f, 0.f};
    float xr[2][4];

#define LOAD_XR(tt) do {                                              \
        const float* xwt_ = xw + (size_t)(tt) * NBATCH * NGATE;       \
        const float* p0_ = xwt_ + (size_t)em0 * NGATE + hs + ej0;     \
        const float* p1_ = xwt_ + (size_t)em1 * NGATE + hs + ej1;     \
        xr[0][0] = p0_[0];       xr[0][1] = p0_[HID];                 \
        xr[0][2] = p0_[2 * HID]; xr[0][3] = p0_[3 * HID];             \
        xr[1][0] = p1_[0];       xr[1][1] = p1_[HID];                 \
        xr[1][2] = p1_[2 * HID]; xr[1][3] = p1_[3 * HID];             \
    } while (0)

    LOAD_XR(0);

#pragma unroll 1
    for (int t = 0; t < TSTEPS; ++t) {
        float acc[2][4][4];
#pragma unroll
        for (int a = 0; a < 2; ++a)
#pragma unroll
            for (int b = 0; b < 4; ++b)
#pragma unroll
                for (int q = 0; q < 4; ++q) acc[a][b][q] = 0.f;

        if (t > 0) {
            const bf16* pAh = hHi + (size_t)(t - 1) * NBATCH * HID + asrc;
            const bf16* pAl = hLo + (size_t)(t - 1) * NBATCH * HID + asrc;
#define STEP_ISSUE(r, s) do {                                                  \
    _Pragma("unroll")                                                          \
    for (int g2 = 0; g2 < 4; ++g2) {                                           \
        const uint32_t d0 = sb + (uint32_t)g2 * A_G_STRIDE +                   \
                            (uint32_t)(s) * A_ST_STRIDE + adst;                \
        const int ko = (8 * g2 + (r)) * 32;                                    \
        cpa16(d0,          pAh + ko);                                          \
        cpa16(d0 + A_PART, pAl + ko);                                          \
    }                                                                          \
    CP_COMMIT(); } while (0)

            STEP_ISSUE(0, 0);
            STEP_ISSUE(1, 1);
            int cst = 0;                     // stage of round r   (= r%3)
            int ist = 2;                     // stage of round r+2 (= (r+2)%3)
            for (int r = 0; r < 8; ++r) {
                if (r < 7) CP_WAIT1(); else CP_WAIT0();   // group r landed
                __syncthreads();             // readers of round r-1 done
                if (r + 2 < 8) STEP_ISSUE(r + 2, ist);
                const uint32_t ab = aGbase + (uint32_t)cst * A_ST_STRIDE;
                const uint32_t bt = (uint32_t)((8 * kg + r) * 2048);
#pragma unroll
                for (int kk = 0; kk < 2; ++kk) {
                    const uint32_t ca = ac16 + (uint32_t)kk * 32;
                    uint32_t ah0[4], ah1[4], al0[4], al1[4];
                    ldsm4(ah0, ab + SWZ(a_row0 + ca));
                    ldsm4(ah1, ab + SWZ(a_row1 + ca));
                    ldsm4(al0, ab + A_PART + SWZ(a_row0 + ca));
                    ldsm4(al1, ab + A_PART + SWZ(a_row1 + ca));
                    uint32_t bhA[4], bhB[4], blA[4], blB[4];
                    ldsm4(bhA, sb + SM_B_HI + bt + SWZ(b_row0 + ca));
                    ldsm4(bhB, sb + SM_B_HI + bt + SWZ(b_row1 + ca));
                    ldsm4(blA, sb + SM_B_LO + bt + SWZ(b_row0 + ca));
                    ldsm4(blB, sb + SM_B_LO + bt + SWZ(b_row1 + ca));
                    // m-half block 0 (rows mhalf*32 + 0..15)
                    mma_nt(acc[0][0], ah0, bhA[0], bhA[2]);
                    mma_nt(acc[0][0], ah0, blA[0], blA[2]);
                    mma_nt(acc[0][0], al0, bhA[0], bhA[2]);
                    mma_nt(acc[0][1], ah0, bhA[1], bhA[3]);
                    mma_nt(acc[0][1], ah0, blA[1], blA[3]);
                    mma_nt(acc[0][1], al0, bhA[1], bhA[3]);
                    mma_nt(acc[0][2], ah0, bhB[0], bhB[2]);
                    mma_nt(acc[0][2], ah0, blB[0], blB[2]);
                    mma_nt(acc[0][2], al0, bhB[0], bhB[2]);
                    mma_nt(acc[0][3], ah0, bhB[1], bhB[3]);
                    mma_nt(acc[0][3], ah0, blB[1], blB[3]);
                    mma_nt(acc[0][3], al0, bhB[1], bhB[3]);
                    // m-half block 1 (rows mhalf*32 + 16..31)
                    mma_nt(acc[1][0], ah1, bhA[0], bhA[2]);
                    mma_nt(acc[1][0], ah1, blA[0], blA[2]);
                    mma_nt(acc[1][0], al1, bhA[0], bhA[2]);
                    mma_nt(acc[1][1], ah1, bhA[1], bhA[3]);
                    mma_nt(acc[1][1], ah1, blA[1], blA[3]);
                    mma_nt(acc[1][1], al1, bhA[1], bhA[3]);
                    mma_nt(acc[1][2], ah1, bhB[0], bhB[2]);
                    mma_nt(acc[1][2], ah1, blB[0], blB[2]);
                    mma_nt(acc[1][2], al1, bhB[0], bhB[2]);
                    mma_nt(acc[1][3], ah1, bhB[1], bhB[3]);
                    mma_nt(acc[1][3], ah1, blB[1], blB[3]);
                    mma_nt(acc[1][3], al1, bhB[1], bhB[3]);
                }
                cst = cst + 1 == 3 ? 0 : cst + 1;
                ist = ist + 1 == 3 ? 0 : ist + 1;
            }
#undef STEP_ISSUE
        }
        __syncthreads();                     // A region free -> sGp alias safe

        // write split-K partials: sGp[kg][row][col], col = gate*8 + hcol
        {
            const int r0 = mhalf * 32 + (lane >> 2);
            const int c0 = (lane & 3) * 2;
#pragma unroll
            for (int mb = 0; mb < 2; ++mb) {
                const int base = kg * 2112 + (r0 + mb * 16) * 33 + c0;
#pragma unroll
                for (int nb = 0; nb < 4; ++nb) {
                    const int idx = base + nb * 8;
                    sGp[idx]              = acc[mb][nb][0];
                    sGp[idx + 1]          = acc[mb][nb][1];
                    sGp[idx + 8 * 33]     = acc[mb][nb][2];
                    sGp[idx + 8 * 33 + 1] = acc[mb][nb][3];
                }
            }
        }
        __syncthreads();

        // epilogue: 64 batch x 8 h-cols = 512 elements; sum 4 k-group partials
        const size_t obase = (size_t)t * NBATCH * HID;
        {
            const int i0 = em0 * 33 + ej0;
            const float ii = sGp[i0] + sGp[i0 + 2112] + sGp[i0 + 4224] + sGp[i0 + 6336] + xr[0][0];
            const int i1 = i0 + 8;
            const float ff = sGp[i1] + sGp[i1 + 2112] + sGp[i1 + 4224] + sGp[i1 + 6336] + xr[0][1];
            const int i2 = i0 + 16;
            const float gg = sGp[i2] + sGp[i2 + 2112] + sGp[i2 + 4224] + sGp[i2 + 6336] + xr[0][2];
            const int i3 = i0 + 24;
            const float oo = sGp[i3] + sGp[i3 + 2112] + sGp[i3 + 4224] + sGp[i3 + 6336] + xr[0][3];
            const float c = sigf(ff) * creg[0] + sigf(ii) * tanhf_fast(gg);
            const float h = sigf(oo) * tanhf_fast(c);
            creg[0] = c;
            const bf16 hh = __float2bfloat16(h);
            const size_t oidx = obase + (size_t)em0 * HID + hs + ej0;
            hHi[oidx] = hh;
            hLo[oidx] = __float2bfloat16(h - __bfloat162float(hh));
            if (outF) outF[oidx] = h;
        }
        {
            const int i0 = em1 * 33 + ej1;
            const float ii = sGp[i0] + sGp[i0 + 2112] + sGp[i0 + 4224] + sGp[i0 + 6336] + xr[1][0];
            const int i1 = i0 + 8;
            const float ff = sGp[i1] + sGp[i1 + 2112] + sGp[i1 + 4224] + sGp[i1 + 6336] + xr[1][1];
            const int i2 = i0 + 16;
            const float gg = sGp[i2] + sGp[i2 + 2112] + sGp[i2 + 4224] + sGp[i2 + 6336] + xr[1][2];
            const int i3 = i0 + 24;
            const float oo = sGp[i3] + sGp[i3 + 2112] + sGp[i3 + 4224] + sGp[i3 + 6336] + xr[1][3];
            const float c = sigf(ff) * creg[1] + sigf(ii) * tanhf_fast(gg);
            const float h = sigf(oo) * tanhf_fast(c);
            creg[1] = c;
            const bf16 hh = __float2bfloat16(h);
            const size_t oidx = obase + (size_t)em1 * HID + hs + ej1;
            hHi[oidx] = hh;
            hLo[oidx] = __float2bfloat16(h - __bfloat162float(hh));
            if (outF) outF[oidx] = h;
        }

        // prefetch next step's xw BEFORE the barrier (overlaps barrier wait)
        if (t + 1 < TSTEPS) LOAD_XR(t + 1);
        grid_barrier<128>();
    }
#undef LOAD_XR
}

// ---------------- host ------------------------------------------------------
extern "C" void kernel_launch(void* const* d_in, const int* in_sizes, int n_in,
                              void* d_out, int out_size) {
    const float* x    = (const float*)d_in[0];
    const float* wih0 = (const float*)d_in[1];
    const float* whh0 = (const float*)d_in[2];
    const float* bih0 = (const float*)d_in[3];
    const float* bhh0 = (const float*)d_in[4];
    const float* wih1 = (const float*)d_in[5];
    const float* whh1 = (const float*)d_in[6];
    const float* bih1 = (const float*)d_in[7];
    const float* bhh1 = (const float*)d_in[8];

    float *xw, *bias;
    bf16 *ahi, *alo, *whi, *wlo;
    cudaGetSymbolAddress((void**)&xw,   g_xw);
    cudaGetSymbolAddress((void**)&ahi,  g_ahi);
    cudaGetSymbolAddress((void**)&alo,  g_alo);
    cudaGetSymbolAddress((void**)&whi,  g_whi);
    cudaGetSymbolAddress((void**)&wlo,  g_wlo);
    cudaGetSymbolAddress((void**)&bias, g_bias);

    cudaFuncSetAttribute(lstm_layer, cudaFuncAttributeMaxDynamicSharedMemorySize,
                         SM_LSTM_TOTAL);

    // launch order fixed so ncu (-s 5 -c 1) profiles lstm_layer (layer 1)
    prep_split<<<4096, 256>>>(x, wih0, whh0, wih1, whh1, ahi, alo, whi, wlo);
    prep_bias<<<32, 256>>>(bih0, bhh0, bih1, bhh1, bias);

    for (int layer = 0; layer < 2; ++layer) {
        const size_t wih_off = (size_t)(2 * layer) * GH;
        const size_t whh_off = (size_t)(2 * layer + 1) * GH;
        gemm_xw<<<dim3(64, 256), 256>>>(ahi, alo, whi + wih_off, wlo + wih_off,
                                        bias + layer * NGATE, xw);
        lstm_layer<<<128, 256, SM_LSTM_TOTAL>>>(whi + whh_off, wlo + whh_off, xw,
                                                ahi, alo,
                                                layer ? (float*)d_out : nullptr);
    }
}